// round 14
// baseline (speedup 1.0000x reference)
#include <cuda_runtime.h>
#include <cuda_bf16.h>
#include <math.h>
#include <stdint.h>

typedef unsigned long long u64;

// ---- scratch (static device globals; no allocation) ----
__device__ __align__(16) float d_XE[(size_t)64 * 32 * 10 * 1024];  // 80MB  [t][b][p][h] = [r][h]
__device__ __align__(16) float d_h[32 * 1024];                     // [b][h]
__device__ __align__(16) float d_c[32 * 1024];                     // [b][h]
__device__ __align__(16) float d_hT[1024 * 32];                    // [h][b]
__device__ __align__(16) float d_embT[1024 * 32];                  // [i][b]
__device__ __align__(16) float d_g2T[4096 * 32];                   // [j][b]
__device__ __align__(16) float d_hWhT[1024 * 32];                  // [h][b]
__device__ __align__(16) float d_WrecB[640 * 8192];                // 20MB: [128 tiles][1024 k][40 s]
__device__ __align__(16) float d_WihB[512 * 8192];                 // 16MB: [128 tiles][1024 k][32 s]
__device__ __align__(16) __nv_bfloat16 d_A2[(size_t)20480 * 2048]; // 80MB [r][hi(1024)|lo(1024)]
__device__ __align__(16) __nv_bfloat16 d_B2T[(size_t)2048 * 1024]; // 4MB  [k: hi|lo][h]
// grid barrier: counter and generation on SEPARATE 128B cache lines
__device__ __align__(128) unsigned d_barc[32];
__device__ __align__(128) unsigned d_barg[32];

// ---- f32x2 helpers ----
static __device__ __forceinline__ u64 dup2f(float a) {
    u64 r; asm("mov.b64 %0,{%1,%1};" : "=l"(r) : "f"(a)); return r;
}
static __device__ __forceinline__ void ffma2(u64& d, u64 a, u64 b) {
    asm("fma.rn.f32x2 %0,%1,%2,%0;" : "+l"(d) : "l"(a), "l"(b));
}
static __device__ __forceinline__ void unpack2(u64 v, float& a, float& b) {
    asm("mov.b64 {%0,%1},%2;" : "=f"(a), "=f"(b) : "l"(v));
}
static __device__ __forceinline__ float sigf(float x) { return 1.0f / (1.0f + expf(-x)); }

// ---- mma.sync helpers (base PTX, compute_103-safe) ----
static __device__ __forceinline__ uint32_t s2u(const void* p) {
    uint32_t a;
    asm("{ .reg .u64 t; cvta.to.shared.u64 t, %1; cvt.u32.u64 %0, t; }" : "=r"(a) : "l"(p));
    return a;
}
static __device__ __forceinline__ void ldsm4(uint32_t* r, uint32_t addr) {
    asm volatile("ldmatrix.sync.aligned.m8n8.x4.shared.b16 {%0,%1,%2,%3},[%4];"
                 : "=r"(r[0]), "=r"(r[1]), "=r"(r[2]), "=r"(r[3]) : "r"(addr));
}
static __device__ __forceinline__ void ldsm4t(uint32_t* r, uint32_t addr) {
    asm volatile("ldmatrix.sync.aligned.m8n8.x4.trans.shared.b16 {%0,%1,%2,%3},[%4];"
                 : "=r"(r[0]), "=r"(r[1]), "=r"(r[2]), "=r"(r[3]) : "r"(addr));
}
static __device__ __forceinline__ void mma16816(float* d, const uint32_t* a, const uint32_t* b) {
    asm volatile(
        "mma.sync.aligned.m16n8k16.row.col.f32.bf16.bf16.f32 "
        "{%0,%1,%2,%3},{%4,%5,%6,%7},{%8,%9},{%0,%1,%2,%3};"
        : "+f"(d[0]), "+f"(d[1]), "+f"(d[2]), "+f"(d[3])
        : "r"(a[0]), "r"(a[1]), "r"(a[2]), "r"(a[3]), "r"(b[0]), "r"(b[1]));
}

// ---- software grid barrier (all blocks resident; padded lines + backoff spin) ----
static __device__ __forceinline__ void gridbar() {
    __syncthreads();
    if (threadIdx.x == 0) {
        __threadfence();
        unsigned g = *(volatile unsigned*)&d_barg[0];
        if (atomicAdd(&d_barc[0], 1u) == gridDim.x - 1) {
            d_barc[0] = 0;
            __threadfence();
            *(volatile unsigned*)&d_barg[0] = g + 1;
        } else {
            while (*(volatile unsigned*)&d_barg[0] == g) { __nanosleep(64); }
            __threadfence();
        }
    }
    __syncthreads();
}

// ---- init: zero recurrent state ----
__global__ void k_init() {
    int i = blockIdx.x * blockDim.x + threadIdx.x;   // 512*256 = 131072
    d_g2T[i] = 0.0f;
    if (i < 32 * 1024) { d_c[i] = 0.0f; d_hWhT[i] = 0.0f; }
}

// ---- prep: Wih -> WihB[tile][k][32], s=(g,hh): j = g*1024 + tile*8 + hh (hh<8) ----
__global__ __launch_bounds__(256) void k_prep_ih(const float* __restrict__ Wih) {
    __shared__ __align__(16) float sm[32][132];
    const int tid = threadIdx.x;
    const int bj = blockIdx.x, k0 = blockIdx.y * 128;
#pragma unroll
    for (int q = 0; q < 4; q++) {                 // 32 rows x 32 float4
        int idx = tid + q * 256;
        int row = idx >> 5, c4 = (idx & 31) * 4;  // row = s = g*8+hh
        int j = (row >> 3) * 1024 + bj * 8 + (row & 7);
        *(float4*)&sm[row][c4] = *(const float4*)&Wih[(size_t)j * 1024 + k0 + c4];
    }
    __syncthreads();
#pragma unroll
    for (int q = 0; q < 4; q++) {                 // 128 k x 8 s4
        int idx = tid + q * 256;
        int kk = idx >> 3, s4 = (idx & 7) * 4;
        float4 v = make_float4(sm[s4][kk], sm[s4 + 1][kk], sm[s4 + 2][kk], sm[s4 + 3][kk]);
        *(float4*)&d_WihB[((size_t)bj * 1024 + k0 + kk) * 32 + s4] = v;
    }
}

// ---- prep: [Whh;Wh] -> WrecB[tile][k][40], j = tile*40 + s ----
__global__ __launch_bounds__(256) void k_prep_rec(const float* __restrict__ Whh,
                                                  const float* __restrict__ Wh) {
    __shared__ __align__(16) float sm[40][132];
    const int tid = threadIdx.x;
    const int tile = blockIdx.x, k0 = blockIdx.y * 128;
#pragma unroll
    for (int q = 0; q < 5; q++) {                 // 40 rows x 32 float4
        int idx = tid + q * 256;
        int row = idx >> 5, c4 = (idx & 31) * 4;
        int j = tile * 40 + row;
        const float* src = (j < 4096) ? (Whh + (size_t)j * 1024) : (Wh + (size_t)(j - 4096) * 1024);
        *(float4*)&sm[row][c4] = *(const float4*)&src[k0 + c4];
    }
    __syncthreads();
#pragma unroll
    for (int q = 0; q < 5; q++) {                 // 128 k x 10 s4
        int idx = tid + q * 256;
        int kk = idx / 10, s4 = (idx % 10) * 4;
        float4 v = make_float4(sm[s4][kk], sm[s4 + 1][kk], sm[s4 + 2][kk], sm[s4 + 3][kk]);
        *(float4*)&d_WrecB[((size_t)tile * 1024 + k0 + kk) * 40 + s4] = v;
    }
}

// ---- cvt: x -> A2 bf16 hi/lo, gathered to r=(t,b,p) row order ----
__global__ __launch_bounds__(256) void k_cvt_x(const float* __restrict__ x) {
    const int B = blockIdx.x;                       // x-order row (b,t,p)
    const int b = B / 640, rem = B % 640, t = rem / 10, p = rem % 10;
    const size_t r = (size_t)(t * 320 + b * 10 + p);
    const int k4 = threadIdx.x * 4;
    float4 v = *(const float4*)(x + (size_t)B * 1024 + k4);
    __nv_bfloat162 hi01 = __floats2bfloat162_rn(v.x, v.y);
    __nv_bfloat162 hi23 = __floats2bfloat162_rn(v.z, v.w);
    float lx = v.x - __bfloat162float(__low2bfloat16(hi01));
    float ly = v.y - __bfloat162float(__high2bfloat16(hi01));
    float lz = v.z - __bfloat162float(__low2bfloat16(hi23));
    float lw = v.w - __bfloat162float(__high2bfloat16(hi23));
    __nv_bfloat162 lo01 = __floats2bfloat162_rn(lx, ly);
    __nv_bfloat162 lo23 = __floats2bfloat162_rn(lz, lw);
    *(__nv_bfloat162*)(d_A2 + r * 2048 + k4)            = hi01;
    *(__nv_bfloat162*)(d_A2 + r * 2048 + k4 + 2)        = hi23;
    *(__nv_bfloat162*)(d_A2 + r * 2048 + 1024 + k4)     = lo01;
    *(__nv_bfloat162*)(d_A2 + r * 2048 + 1024 + k4 + 2) = lo23;
}

// ---- cvt: Wx -> B2T transposed bf16 hi/lo: B2T[k][h] ----
__global__ __launch_bounds__(256) void k_cvt_w(const float* __restrict__ Wx) {
    __shared__ __align__(16) unsigned short s_hi[64][40];
    __shared__ __align__(16) unsigned short s_lo[64][40];
    const int tid = threadIdx.x;
    const int k0 = blockIdx.x * 64, h0 = blockIdx.y * 32;
    {
        int hl = tid >> 3, kq = (tid & 7) * 8;
        const float* src = Wx + (size_t)(h0 + hl) * 1024 + k0 + kq;
        float4 v0 = *(const float4*)src;
        float4 v1 = *(const float4*)(src + 4);
        float vv[8] = {v0.x, v0.y, v0.z, v0.w, v1.x, v1.y, v1.z, v1.w};
#pragma unroll
        for (int j = 0; j < 8; j++) {
            __nv_bfloat16 hb = __float2bfloat16_rn(vv[j]);
            float lo = vv[j] - __bfloat162float(hb);
            __nv_bfloat16 lb = __float2bfloat16_rn(lo);
            s_hi[kq + j][hl] = *(unsigned short*)&hb;
            s_lo[kq + j][hl] = *(unsigned short*)&lb;
        }
    }
    __syncthreads();
    int kl = tid >> 2, hq = (tid & 3) * 8;
    uint4 hv = *(const uint4*)&s_hi[kl][hq];
    uint4 lv = *(const uint4*)&s_lo[kl][hq];
    *(uint4*)(d_B2T + (size_t)(k0 + kl) * 1024 + h0 + hq)        = hv;
    *(uint4*)(d_B2T + (size_t)(1024 + k0 + kl) * 1024 + h0 + hq) = lv;
}

// ---- K0 via mma.sync bf16: XE = A2 x B2T, 3-segment split folded into K=3072 ----
#define SA_BYTES (128 * 144)       // 18432
#define SB_BYTES (64 * 272)        // 17408
#define XE_SMEM (2 * SA_BYTES + 2 * SB_BYTES)   // 71680

static __device__ __forceinline__ void xe_load_chunk(char* dsm, int buf, int c,
                                                     int m0, int n0, int tid) {
    const int seg = c >> 4, kc = (c & 15) << 6;
    const int aoff = (seg == 2) ? 1024 : 0;
    const int boff = (seg == 1) ? 1024 : 0;
    {
        int row = tid >> 1, half = tid & 1;
        const uint4* src = (const uint4*)(d_A2 + (size_t)(m0 + row) * 2048 + aoff + kc + half * 32);
        char* dst = dsm + buf * SA_BYTES + row * 144 + half * 64;
#pragma unroll
        for (int j = 0; j < 4; j++) *(uint4*)(dst + j * 16) = src[j];
    }
    {
        int row = tid >> 2, q = tid & 3;
        const uint4* src = (const uint4*)(d_B2T + (size_t)(boff + kc + row) * 1024 + n0 + q * 32);
        char* dst = dsm + 2 * SA_BYTES + buf * SB_BYTES + row * 272 + q * 64;
#pragma unroll
        for (int j = 0; j < 4; j++) *(uint4*)(dst + j * 16) = src[j];
    }
}

__global__ __launch_bounds__(256, 2) void k_xe_mma() {
    extern __shared__ __align__(16) char dsm[];
    const int tid = threadIdx.x, wid = tid >> 5, lane = tid & 31;
    const int m0 = (blockIdx.x >> 3) * 128, n0 = (blockIdx.x & 7) * 128;
    const int wm = wid >> 2, wn = wid & 3;           // warp tile: 64m x 32n
    const uint32_t smem0 = s2u(dsm);

    float acc[4][4][4];
#pragma unroll
    for (int i = 0; i < 4; i++)
#pragma unroll
        for (int j = 0; j < 4; j++)
#pragma unroll
            for (int q = 0; q < 4; q++) acc[i][j][q] = 0.0f;

    xe_load_chunk(dsm, 0, 0, m0, n0, tid);
    __syncthreads();

    for (int c = 0; c < 48; c++) {
        if (c + 1 < 48) xe_load_chunk(dsm, (c + 1) & 1, c + 1, m0, n0, tid);
        const uint32_t Ab = smem0 + (c & 1) * SA_BYTES;
        const uint32_t Bb = smem0 + 2 * SA_BYTES + (c & 1) * SB_BYTES;
        const uint32_t arow = (lane & 15), ahalf = (lane >> 4) * 8;
#pragma unroll
        for (int ks = 0; ks < 4; ks++) {
            const int kk = ks * 16;
            uint32_t a[4][4];
#pragma unroll
            for (int mt = 0; mt < 4; mt++)
                ldsm4(a[mt], Ab + (wm * 64 + mt * 16 + arow) * 144 + (kk + ahalf) * 2);
            uint32_t bfr[2][4];
#pragma unroll
            for (int pr = 0; pr < 2; pr++)
                ldsm4t(bfr[pr], Bb + (kk + arow) * 272 + (wn * 32 + pr * 16 + ahalf) * 2);
#pragma unroll
            for (int mt = 0; mt < 4; mt++) {
#pragma unroll
                for (int nt = 0; nt < 4; nt++) {
                    mma16816(acc[mt][nt], a[mt], &bfr[nt >> 1][(nt & 1) * 2]);
                }
            }
        }
        __syncthreads();
    }

#pragma unroll
    for (int mt = 0; mt < 4; mt++) {
#pragma unroll
        for (int nt = 0; nt < 4; nt++) {
            int row = m0 + wm * 64 + mt * 16 + (lane >> 2);
            int col = n0 + wn * 32 + nt * 8 + (lane & 3) * 2;
            *(float2*)(d_XE + (size_t)row * 1024 + col) =
                make_float2(acc[mt][nt][0], acc[mt][nt][1]);
            *(float2*)(d_XE + (size_t)(row + 8) * 1024 + col) =
                make_float2(acc[mt][nt][2], acc[mt][nt][3]);
        }
    }
}

// ---- attn(t): 32 blocks x 1024 thr. scores -> softmax(P=10) -> pooled embT ----
__global__ __launch_bounds__(1024) void k_attn(int t, const float* __restrict__ x,
                                               const float* __restrict__ b_att,
                                               const float* __restrict__ v) {
    const int b = blockIdx.x, tid = threadIdx.x;
    __shared__ float sm[10][33];
    __shared__ float al[10];
    const int h = tid;
    const float base = d_hWhT[h * 32 + b] + b_att[h];
    const float vh = v[h];
    const float* xe = d_XE + (size_t)(t * 32 + b) * 10240;
    float ps[10];
#pragma unroll
    for (int p = 0; p < 10; p++) ps[p] = tanhf(xe[p * 1024 + h] + base) * vh;
    const int lane = tid & 31, w = tid >> 5;
#pragma unroll
    for (int p = 0; p < 10; p++) {
        float s = ps[p];
#pragma unroll
        for (int off = 16; off; off >>= 1) s += __shfl_xor_sync(0xffffffffu, s, off);
        if (lane == 0) sm[p][w] = s;
    }
    __syncthreads();
    if (tid < 320) {
        int p = tid >> 5;
        float s = sm[p][lane];
#pragma unroll
        for (int off = 16; off; off >>= 1) s += __shfl_xor_sync(0xffffffffu, s, off);
        if (lane == 0) sm[p][32] = s;
    }
    __syncthreads();
    if (tid == 0) {
        float sc[10], mx = -1e30f;
#pragma unroll
        for (int p = 0; p < 10; p++) { sc[p] = sm[p][32]; mx = fmaxf(mx, sc[p]); }
        float den = 0.0f;
#pragma unroll
        for (int p = 0; p < 10; p++) { sc[p] = expf(sc[p] - mx); den += sc[p]; }
        float inv = 1.0f / den;
#pragma unroll
        for (int p = 0; p < 10; p++) al[p] = sc[p] * inv;
    }
    __syncthreads();
    float a[10];
#pragma unroll
    for (int p = 0; p < 10; p++) a[p] = al[p];
    const float* xb = x + (size_t)(b * 64 + t) * 10240;
    float s = 0.0f;
#pragma unroll
    for (int p = 0; p < 10; p++) s = fmaf(a[p], xb[p * 1024 + tid], s);
    d_embT[tid * 32 + b] = s;
}

// ---- fused step: gates (128 blocks x 32 j) -> gridbar -> rec (128 blocks x 40 j) ----
// dyn smem: max(32*4096 + 32*32*32*4, 40*4096 + 8*40*32*4) = max(163840, 204800) = 204800
#define STEP_SMEM 204800

__global__ __launch_bounds__(256) void k_step(int dorec,
                                              const float* __restrict__ bih,
                                              const float* __restrict__ bhh) {
    extern __shared__ __align__(16) char dsm[];
    __shared__ float gvs[32][33];
    const int tid = threadIdx.x, bid = blockIdx.x;
    const int w = tid >> 5, lane = tid & 31;

    // ---- gates phase: tile bid owns h cols {bid*8..bid*8+7} x 4 gates (32 j) ----
    {
        float* ws = (float*)dsm;                       // [1024][32]
        float* ps = (float*)(dsm + 131072);            // [8][32][32]
        const int bj = bid;
        const float4* wb = (const float4*)(d_WihB + (size_t)bj * 32768);
#pragma unroll
        for (int i = 0; i < 32; i++) ((float4*)ws)[tid + i * 256] = wb[tid + i * 256];
        __syncthreads();
        u64 acc[16];
#pragma unroll
        for (int q = 0; q < 16; q++) acc[q] = 0ull;
        const float* eb = d_embT + w * 128 * 32 + lane;
#pragma unroll 2
        for (int k = 0; k < 128; k++) {
            u64 ed = dup2f(eb[k * 32]);
            const ulonglong2* wrow = (const ulonglong2*)(ws + (w * 128 + k) * 32);
#pragma unroll
            for (int j = 0; j < 8; j++) {
                ulonglong2 t2 = wrow[j];
                ffma2(acc[2 * j], ed, t2.x); ffma2(acc[2 * j + 1], ed, t2.y);
            }
        }
#pragma unroll
        for (int q = 0; q < 16; q++) {
            float a2, b2; unpack2(acc[q], a2, b2);
            ps[(w * 32 + 2 * q) * 32 + lane] = a2;
            ps[(w * 32 + 2 * q + 1) * 32 + lane] = b2;
        }
        __syncthreads();
#pragma unroll
        for (int q = 0; q < 4; q++) {                  // 32 s x 32 b = 1024 outs
            int idx = tid + q * 256;
            int s = idx >> 5, b = idx & 31;
            float r = 0.0f;
#pragma unroll
            for (int w8 = 0; w8 < 8; w8++) r += ps[(w8 * 32 + s) * 32 + b];
            int j = (s >> 3) * 1024 + bj * 8 + (s & 7);
            r += d_g2T[j * 32 + b] + bih[j] + bhh[j];
            gvs[s][b] = r;
        }
        __syncthreads();
        {   // cell update: 256 thr = 32 b x 8 h
            int b = tid >> 3, hh = tid & 7;
            int h = bj * 8 + hh;
            float iv = gvs[hh][b], fv = gvs[8 + hh][b];
            float gv = gvs[16 + hh][b], ov = gvs[24 + hh][b];
            float c = d_c[b * 1024 + h];
            float cn = sigf(fv) * c + sigf(iv) * tanhf(gv);
            float hn = sigf(ov) * tanhf(cn);
            d_c[b * 1024 + h] = cn;
            d_h[b * 1024 + h] = hn;
            d_hT[h * 32 + b] = hn;
        }
    }

    // ---- rec phase: tile bid owns j = bid*40 .. bid*40+39 ----
    if (dorec) {
        gridbar();
        float* ws = (float*)dsm;                       // [1024][40]
        float* ps = (float*)(dsm + 163840);            // [8][40][32]
        const int tile = bid;
        const float4* wb = (const float4*)(d_WrecB + (size_t)tile * 40960);
#pragma unroll
        for (int i = 0; i < 40; i++) ((float4*)ws)[tid + i * 256] = wb[tid + i * 256];
        __syncthreads();
        u64 acc[20];
#pragma unroll
        for (int q = 0; q < 20; q++) acc[q] = 0ull;
        const float* eb = d_hT + w * 128 * 32 + lane;
#pragma unroll 2
        for (int k = 0; k < 128; k++) {
            u64 ed = dup2f(eb[k * 32]);
            const ulonglong2* wrow = (const ulonglong2*)(ws + (w * 128 + k) * 40);
#pragma unroll
            for (int j = 0; j < 10; j++) {
                ulonglong2 t2 = wrow[j];
                ffma2(acc[2 * j], ed, t2.x); ffma2(acc[2 * j + 1], ed, t2.y);
            }
        }
#pragma unroll
        for (int q = 0; q < 20; q++) {
            float a2, b2; unpack2(acc[q], a2, b2);
            ps[(w * 40 + 2 * q) * 32 + lane] = a2;
            ps[(w * 40 + 2 * q + 1) * 32 + lane] = b2;
        }
        __syncthreads();
#pragma unroll
        for (int q = 0; q < 5; q++) {                  // 40 s x 32 b = 1280 outs
            int idx = tid + q * 256;
            int s = idx >> 5, b = idx & 31;
            float r = 0.0f;
#pragma unroll
            for (int w8 = 0; w8 < 8; w8++) r += ps[(w8 * 40 + s) * 32 + b];
            int j = tile * 40 + s;
            if (j < 4096) d_g2T[j * 32 + b] = r;
            else          d_hWhT[(j - 4096) * 32 + b] = r;
        }
    }
}

// ---- final FC ----
__global__ __launch_bounds__(256) void k_fc(const float* __restrict__ Wfc,
                                            const float* __restrict__ bfc,
                                            float* __restrict__ out) {
    const int b = blockIdx.x, w = threadIdx.x >> 5, lane = threadIdx.x & 31;
    const float* hr = d_h + b * 1024;
    const float* wr = Wfc + w * 1024;
    float s = 0.0f;
    for (int i = lane * 4; i < 1024; i += 128) {
        float4 hv = *(const float4*)&hr[i];
        float4 wv = *(const float4*)&wr[i];
        s = fmaf(hv.x, wv.x, s); s = fmaf(hv.y, wv.y, s);
        s = fmaf(hv.z, wv.z, s); s = fmaf(hv.w, wv.w, s);
    }
#pragma unroll
    for (int off = 16; off; off >>= 1) s += __shfl_xor_sync(0xffffffffu, s, off);
    if (lane == 0) out[b * 8 + w] = s + bfc[w];
}

extern "C" void kernel_launch(void* const* d_in, const int* in_sizes, int n_in,
                              void* d_out, int out_size) {
    const float* x     = (const float*)d_in[0];
    const float* Wx    = (const float*)d_in[1];
    const float* Wh    = (const float*)d_in[2];
    const float* b_att = (const float*)d_in[3];
    const float* v     = (const float*)d_in[4];
    const float* Wih   = (const float*)d_in[5];
    const float* Whh   = (const float*)d_in[6];
    const float* bih   = (const float*)d_in[7];
    const float* bhh   = (const float*)d_in[8];
    const float* Wfc   = (const float*)d_in[9];
    const float* bfc   = (const float*)d_in[10];
    float* out = (float*)d_out;

    static int attr_set = 0;
    if (!attr_set) {
        cudaFuncSetAttribute(k_xe_mma, cudaFuncAttributeMaxDynamicSharedMemorySize, XE_SMEM);
        cudaFuncSetAttribute(k_step, cudaFuncAttributeMaxDynamicSharedMemorySize, STEP_SMEM);
        cudaFuncSetAttribute(k_step, cudaFuncAttributePreferredSharedMemoryCarveout, 100);
        attr_set = 1;
    }

    k_init<<<512, 256>>>();
    k_prep_rec<<<dim3(128, 8), 256>>>(Whh, Wh);
    k_prep_ih<<<dim3(128, 8), 256>>>(Wih);
    k_cvt_x<<<20480, 256>>>(x);
    k_cvt_w<<<dim3(16, 32), 256>>>(Wx);
    k_xe_mma<<<1280, 256, XE_SMEM>>>();
    for (int t = 0; t < 64; t++) {
        k_attn<<<32, 1024>>>(t, x, b_att, v);
        k_step<<<128, 256, STEP_SMEM>>>(t < 63 ? 1 : 0, bih, bhh);
    }
    k_fc<<<32, 256>>>(Wfc, bfc, out);
}

// round 16
// speedup vs baseline: 1.4398x; 1.4398x over previous
#include <cuda_runtime.h>
#include <cuda_bf16.h>
#include <math.h>
#include <stdint.h>

typedef unsigned long long u64;

// ---- scratch (static device globals; no allocation) ----
__device__ __align__(16) float d_XE[(size_t)64 * 32 * 10 * 1024];  // 80MB  [t][b][p][h] = [r][h]
__device__ __align__(16) float d_h[32 * 1024];                     // [b][h]
__device__ __align__(16) float d_c[32 * 1024];                     // [b][h]
__device__ __align__(16) float d_hT[1024 * 32];                    // [h][b]
__device__ __align__(16) float d_embT[1024 * 32];                  // [i][b]
__device__ __align__(16) float d_g2T[4096 * 32];                   // [j][b]
__device__ __align__(16) float d_hWhT[1024 * 32];                  // [h][b]
__device__ __align__(16) float d_WrecB[640 * 8192];                // 20MB: [256 tiles][1024 k][20 s]
__device__ __align__(16) float d_WihB[512 * 8192];                 // 16MB: [256 tiles][1024 k][16 s]
__device__ __align__(16) __nv_bfloat16 d_A2[(size_t)20480 * 2048]; // 80MB [r][hi(1024)|lo(1024)]
__device__ __align__(16) __nv_bfloat16 d_B2T[(size_t)2048 * 1024]; // 4MB  [k: hi|lo][h]
// grid barrier: counter and generation on SEPARATE 128B cache lines
__device__ __align__(128) unsigned d_barc[32];
__device__ __align__(128) unsigned d_barg[32];

// ---- f32x2 helpers ----
static __device__ __forceinline__ u64 dup2f(float a) {
    u64 r; asm("mov.b64 %0,{%1,%1};" : "=l"(r) : "f"(a)); return r;
}
static __device__ __forceinline__ void ffma2(u64& d, u64 a, u64 b) {
    asm("fma.rn.f32x2 %0,%1,%2,%0;" : "+l"(d) : "l"(a), "l"(b));
}
static __device__ __forceinline__ void unpack2(u64 v, float& a, float& b) {
    asm("mov.b64 {%0,%1},%2;" : "=f"(a), "=f"(b) : "l"(v));
}
static __device__ __forceinline__ float sigf(float x) { return 1.0f / (1.0f + expf(-x)); }

// ---- mma.sync helpers (base PTX, compute_103-safe) ----
static __device__ __forceinline__ uint32_t s2u(const void* p) {
    uint32_t a;
    asm("{ .reg .u64 t; cvta.to.shared.u64 t, %1; cvt.u32.u64 %0, t; }" : "=r"(a) : "l"(p));
    return a;
}
static __device__ __forceinline__ void ldsm4(uint32_t* r, uint32_t addr) {
    asm volatile("ldmatrix.sync.aligned.m8n8.x4.shared.b16 {%0,%1,%2,%3},[%4];"
                 : "=r"(r[0]), "=r"(r[1]), "=r"(r[2]), "=r"(r[3]) : "r"(addr));
}
static __device__ __forceinline__ void ldsm4t(uint32_t* r, uint32_t addr) {
    asm volatile("ldmatrix.sync.aligned.m8n8.x4.trans.shared.b16 {%0,%1,%2,%3},[%4];"
                 : "=r"(r[0]), "=r"(r[1]), "=r"(r[2]), "=r"(r[3]) : "r"(addr));
}
static __device__ __forceinline__ void mma16816(float* d, const uint32_t* a, const uint32_t* b) {
    asm volatile(
        "mma.sync.aligned.m16n8k16.row.col.f32.bf16.bf16.f32 "
        "{%0,%1,%2,%3},{%4,%5,%6,%7},{%8,%9},{%0,%1,%2,%3};"
        : "+f"(d[0]), "+f"(d[1]), "+f"(d[2]), "+f"(d[3])
        : "r"(a[0]), "r"(a[1]), "r"(a[2]), "r"(a[3]), "r"(b[0]), "r"(b[1]));
}

// ---- software grid barrier (all blocks resident; padded lines + backoff spin) ----
static __device__ __forceinline__ void gridbar() {
    __syncthreads();
    if (threadIdx.x == 0) {
        __threadfence();
        unsigned g = *(volatile unsigned*)&d_barg[0];
        if (atomicAdd(&d_barc[0], 1u) == gridDim.x - 1) {
            d_barc[0] = 0;
            __threadfence();
            *(volatile unsigned*)&d_barg[0] = g + 1;
        } else {
            while (*(volatile unsigned*)&d_barg[0] == g) { __nanosleep(64); }
            __threadfence();
        }
    }
    __syncthreads();
}

// ---- init: zero recurrent state ----
__global__ void k_init() {
    int i = blockIdx.x * blockDim.x + threadIdx.x;   // 512*256 = 131072
    d_g2T[i] = 0.0f;
    if (i < 32 * 1024) { d_c[i] = 0.0f; d_hWhT[i] = 0.0f; }
}

// ---- prep: Wih -> WihB[tile][k][16], s=(g,hh): j = g*1024 + tile*4 + hh (hh<4) ----
__global__ __launch_bounds__(256) void k_prep_ih(const float* __restrict__ Wih) {
    __shared__ __align__(16) float sm[16][132];
    const int tid = threadIdx.x;
    const int bj = blockIdx.x, k0 = blockIdx.y * 128;
#pragma unroll
    for (int q = 0; q < 2; q++) {                 // 16 rows x 32 float4
        int idx = tid + q * 256;
        int row = idx >> 5, c4 = (idx & 31) * 4;  // row = s = g*4+hh
        int j = (row >> 2) * 1024 + bj * 4 + (row & 3);
        *(float4*)&sm[row][c4] = *(const float4*)&Wih[(size_t)j * 1024 + k0 + c4];
    }
    __syncthreads();
#pragma unroll
    for (int q = 0; q < 2; q++) {                 // 128 k x 4 s4
        int idx = tid + q * 256;
        int kk = idx >> 2, s4 = (idx & 3) * 4;
        float4 v = make_float4(sm[s4][kk], sm[s4 + 1][kk], sm[s4 + 2][kk], sm[s4 + 3][kk]);
        *(float4*)&d_WihB[((size_t)bj * 1024 + k0 + kk) * 16 + s4] = v;
    }
}

// ---- prep: [Whh;Wh] -> WrecB[tile][k][20], j = tile*20 + s ----
__global__ __launch_bounds__(256) void k_prep_rec(const float* __restrict__ Whh,
                                                  const float* __restrict__ Wh) {
    __shared__ __align__(16) float sm[20][132];
    const int tid = threadIdx.x;
    const int tile = blockIdx.x, k0 = blockIdx.y * 128;
#pragma unroll
    for (int q = 0; q < 3; q++) {                 // 20 rows x 32 float4 = 640
        int idx = tid + q * 256;
        if (idx < 640) {
            int row = idx >> 5, c4 = (idx & 31) * 4;
            int j = tile * 20 + row;
            const float* src = (j < 4096) ? (Whh + (size_t)j * 1024)
                                          : (Wh + (size_t)(j - 4096) * 1024);
            *(float4*)&sm[row][c4] = *(const float4*)&src[k0 + c4];
        }
    }
    __syncthreads();
#pragma unroll
    for (int q = 0; q < 3; q++) {                 // 128 k x 5 s4 = 640
        int idx = tid + q * 256;
        if (idx < 640) {
            int kk = idx / 5, s4 = (idx % 5) * 4;
            float4 v = make_float4(sm[s4][kk], sm[s4 + 1][kk], sm[s4 + 2][kk], sm[s4 + 3][kk]);
            *(float4*)&d_WrecB[((size_t)tile * 1024 + k0 + kk) * 20 + s4] = v;
        }
    }
}

// ---- cvt: x -> A2 bf16 hi/lo, gathered to r=(t,b,p) row order ----
__global__ __launch_bounds__(256) void k_cvt_x(const float* __restrict__ x) {
    const int B = blockIdx.x;                       // x-order row (b,t,p)
    const int b = B / 640, rem = B % 640, t = rem / 10, p = rem % 10;
    const size_t r = (size_t)(t * 320 + b * 10 + p);
    const int k4 = threadIdx.x * 4;
    float4 v = *(const float4*)(x + (size_t)B * 1024 + k4);
    __nv_bfloat162 hi01 = __floats2bfloat162_rn(v.x, v.y);
    __nv_bfloat162 hi23 = __floats2bfloat162_rn(v.z, v.w);
    float lx = v.x - __bfloat162float(__low2bfloat16(hi01));
    float ly = v.y - __bfloat162float(__high2bfloat16(hi01));
    float lz = v.z - __bfloat162float(__low2bfloat16(hi23));
    float lw = v.w - __bfloat162float(__high2bfloat16(hi23));
    __nv_bfloat162 lo01 = __floats2bfloat162_rn(lx, ly);
    __nv_bfloat162 lo23 = __floats2bfloat162_rn(lz, lw);
    *(__nv_bfloat162*)(d_A2 + r * 2048 + k4)            = hi01;
    *(__nv_bfloat162*)(d_A2 + r * 2048 + k4 + 2)        = hi23;
    *(__nv_bfloat162*)(d_A2 + r * 2048 + 1024 + k4)     = lo01;
    *(__nv_bfloat162*)(d_A2 + r * 2048 + 1024 + k4 + 2) = lo23;
}

// ---- cvt: Wx -> B2T transposed bf16 hi/lo: B2T[k][h] ----
__global__ __launch_bounds__(256) void k_cvt_w(const float* __restrict__ Wx) {
    __shared__ __align__(16) unsigned short s_hi[64][40];
    __shared__ __align__(16) unsigned short s_lo[64][40];
    const int tid = threadIdx.x;
    const int k0 = blockIdx.x * 64, h0 = blockIdx.y * 32;
    {
        int hl = tid >> 3, kq = (tid & 7) * 8;
        const float* src = Wx + (size_t)(h0 + hl) * 1024 + k0 + kq;
        float4 v0 = *(const float4*)src;
        float4 v1 = *(const float4*)(src + 4);
        float vv[8] = {v0.x, v0.y, v0.z, v0.w, v1.x, v1.y, v1.z, v1.w};
#pragma unroll
        for (int j = 0; j < 8; j++) {
            __nv_bfloat16 hb = __float2bfloat16_rn(vv[j]);
            float lo = vv[j] - __bfloat162float(hb);
            __nv_bfloat16 lb = __float2bfloat16_rn(lo);
            s_hi[kq + j][hl] = *(unsigned short*)&hb;
            s_lo[kq + j][hl] = *(unsigned short*)&lb;
        }
    }
    __syncthreads();
    int kl = tid >> 2, hq = (tid & 3) * 8;
    uint4 hv = *(const uint4*)&s_hi[kl][hq];
    uint4 lv = *(const uint4*)&s_lo[kl][hq];
    *(uint4*)(d_B2T + (size_t)(k0 + kl) * 1024 + h0 + hq)        = hv;
    *(uint4*)(d_B2T + (size_t)(1024 + k0 + kl) * 1024 + h0 + hq) = lv;
}

// ---- K0 via mma.sync bf16: XE = A2 x B2T, 3-segment split folded into K=3072 ----
#define SA_BYTES (128 * 144)       // 18432
#define SB_BYTES (64 * 272)        // 17408
#define XE_SMEM (2 * SA_BYTES + 2 * SB_BYTES)   // 71680

static __device__ __forceinline__ void xe_load_chunk(char* dsm, int buf, int c,
                                                     int m0, int n0, int tid) {
    const int seg = c >> 4, kc = (c & 15) << 6;
    const int aoff = (seg == 2) ? 1024 : 0;
    const int boff = (seg == 1) ? 1024 : 0;
    {
        int row = tid >> 1, half = tid & 1;
        const uint4* src = (const uint4*)(d_A2 + (size_t)(m0 + row) * 2048 + aoff + kc + half * 32);
        char* dst = dsm + buf * SA_BYTES + row * 144 + half * 64;
#pragma unroll
        for (int j = 0; j < 4; j++) *(uint4*)(dst + j * 16) = src[j];
    }
    {
        int row = tid >> 2, q = tid & 3;
        const uint4* src = (const uint4*)(d_B2T + (size_t)(boff + kc + row) * 1024 + n0 + q * 32);
        char* dst = dsm + 2 * SA_BYTES + buf * SB_BYTES + row * 272 + q * 64;
#pragma unroll
        for (int j = 0; j < 4; j++) *(uint4*)(dst + j * 16) = src[j];
    }
}

__global__ __launch_bounds__(256, 2) void k_xe_mma() {
    extern __shared__ __align__(16) char dsm[];
    const int tid = threadIdx.x, wid = tid >> 5, lane = tid & 31;
    const int m0 = (blockIdx.x >> 3) * 128, n0 = (blockIdx.x & 7) * 128;
    const int wm = wid >> 2, wn = wid & 3;           // warp tile: 64m x 32n
    const uint32_t smem0 = s2u(dsm);

    float acc[4][4][4];
#pragma unroll
    for (int i = 0; i < 4; i++)
#pragma unroll
        for (int j = 0; j < 4; j++)
#pragma unroll
            for (int q = 0; q < 4; q++) acc[i][j][q] = 0.0f;

    xe_load_chunk(dsm, 0, 0, m0, n0, tid);
    __syncthreads();

    for (int c = 0; c < 48; c++) {
        if (c + 1 < 48) xe_load_chunk(dsm, (c + 1) & 1, c + 1, m0, n0, tid);
        const uint32_t Ab = smem0 + (c & 1) * SA_BYTES;
        const uint32_t Bb = smem0 + 2 * SA_BYTES + (c & 1) * SB_BYTES;
        const uint32_t arow = (lane & 15), ahalf = (lane >> 4) * 8;
#pragma unroll
        for (int ks = 0; ks < 4; ks++) {
            const int kk = ks * 16;
            uint32_t a[4][4];
#pragma unroll
            for (int mt = 0; mt < 4; mt++)
                ldsm4(a[mt], Ab + (wm * 64 + mt * 16 + arow) * 144 + (kk + ahalf) * 2);
            uint32_t bfr[2][4];
#pragma unroll
            for (int pr = 0; pr < 2; pr++)
                ldsm4t(bfr[pr], Bb + (kk + arow) * 272 + (wn * 32 + pr * 16 + ahalf) * 2);
#pragma unroll
            for (int mt = 0; mt < 4; mt++) {
#pragma unroll
                for (int nt = 0; nt < 4; nt++) {
                    mma16816(acc[mt][nt], a[mt], &bfr[nt >> 1][(nt & 1) * 2]);
                }
            }
        }
        __syncthreads();
    }

#pragma unroll
    for (int mt = 0; mt < 4; mt++) {
#pragma unroll
        for (int nt = 0; nt < 4; nt++) {
            int row = m0 + wm * 64 + mt * 16 + (lane >> 2);
            int col = n0 + wn * 32 + nt * 8 + (lane & 3) * 2;
            *(float2*)(d_XE + (size_t)row * 1024 + col) =
                make_float2(acc[mt][nt][0], acc[mt][nt][1]);
            *(float2*)(d_XE + (size_t)(row + 8) * 1024 + col) =
                make_float2(acc[mt][nt][2], acc[mt][nt][3]);
        }
    }
}

// ---- attn(t): 32 blocks x 1024 thr. scores -> softmax(P=10) -> pooled embT ----
__global__ __launch_bounds__(1024) void k_attn(int t, const float* __restrict__ x,
                                               const float* __restrict__ b_att,
                                               const float* __restrict__ v) {
    const int b = blockIdx.x, tid = threadIdx.x;
    __shared__ float sm[10][33];
    __shared__ float al[10];
    const int h = tid;
    const float base = d_hWhT[h * 32 + b] + b_att[h];
    const float vh = v[h];
    const float* xe = d_XE + (size_t)(t * 32 + b) * 10240;
    float ps[10];
#pragma unroll
    for (int p = 0; p < 10; p++) ps[p] = tanhf(xe[p * 1024 + h] + base) * vh;
    const int lane = tid & 31, w = tid >> 5;
#pragma unroll
    for (int p = 0; p < 10; p++) {
        float s = ps[p];
#pragma unroll
        for (int off = 16; off; off >>= 1) s += __shfl_xor_sync(0xffffffffu, s, off);
        if (lane == 0) sm[p][w] = s;
    }
    __syncthreads();
    if (tid < 320) {
        int p = tid >> 5;
        float s = sm[p][lane];
#pragma unroll
        for (int off = 16; off; off >>= 1) s += __shfl_xor_sync(0xffffffffu, s, off);
        if (lane == 0) sm[p][32] = s;
    }
    __syncthreads();
    if (tid == 0) {
        float sc[10], mx = -1e30f;
#pragma unroll
        for (int p = 0; p < 10; p++) { sc[p] = sm[p][32]; mx = fmaxf(mx, sc[p]); }
        float den = 0.0f;
#pragma unroll
        for (int p = 0; p < 10; p++) { sc[p] = expf(sc[p] - mx); den += sc[p]; }
        float inv = 1.0f / den;
#pragma unroll
        for (int p = 0; p < 10; p++) al[p] = sc[p] * inv;
    }
    __syncthreads();
    float a[10];
#pragma unroll
    for (int p = 0; p < 10; p++) a[p] = al[p];
    const float* xb = x + (size_t)(b * 64 + t) * 10240;
    float s = 0.0f;
#pragma unroll
    for (int p = 0; p < 10; p++) s = fmaf(a[p], xb[p * 1024 + tid], s);
    d_embT[tid * 32 + b] = s;
}

// ---- fused step: gates (256 blk x 16 j) -> gridbar -> rec (256 blk x 20 j) ----
// dyn smem: max(16*4096 + 8*16*32*4, 20*4096 + 8*20*32*4) = max(81920, 102400) = 102400
#define STEP_SMEM 102400

__global__ __launch_bounds__(256, 2) void k_step(int dorec,
                                                 const float* __restrict__ bih,
                                                 const float* __restrict__ bhh) {
    extern __shared__ __align__(16) char dsm[];
    __shared__ float gvs[16][33];
    const int tid = threadIdx.x, bid = blockIdx.x;
    const int w = tid >> 5, lane = tid & 31;

    // ---- gates phase: tile bid owns h cols {bid*4..bid*4+3} x 4 gates (16 j) ----
    {
        float* ws = (float*)dsm;                       // [1024][16]
        float* ps = (float*)(dsm + 65536);             // [8][16][32]
        const int bj = bid;
        const float4* wb = (const float4*)(d_WihB + (size_t)bj * 16384);
#pragma unroll
        for (int i = 0; i < 16; i++) ((float4*)ws)[tid + i * 256] = wb[tid + i * 256];
        __syncthreads();
        u64 acc[8];
#pragma unroll
        for (int q = 0; q < 8; q++) acc[q] = 0ull;
        const float* eb = d_embT + w * 128 * 32 + lane;
#pragma unroll 4
        for (int k = 0; k < 128; k++) {
            u64 ed = dup2f(eb[k * 32]);
            const ulonglong2* wrow = (const ulonglong2*)(ws + (w * 128 + k) * 16);
#pragma unroll
            for (int j = 0; j < 4; j++) {
                ulonglong2 t2 = wrow[j];
                ffma2(acc[2 * j], ed, t2.x); ffma2(acc[2 * j + 1], ed, t2.y);
            }
        }
#pragma unroll
        for (int q = 0; q < 8; q++) {
            float a2, b2; unpack2(acc[q], a2, b2);
            ps[(w * 16 + 2 * q) * 32 + lane] = a2;
            ps[(w * 16 + 2 * q + 1) * 32 + lane] = b2;
        }
        __syncthreads();
#pragma unroll
        for (int q = 0; q < 2; q++) {                  // 16 s x 32 b = 512 outs
            int idx = tid + q * 256;
            int s = idx >> 5, b = idx & 31;
            float r = 0.0f;
#pragma unroll
            for (int w8 = 0; w8 < 8; w8++) r += ps[(w8 * 16 + s) * 32 + b];
            int j = (s >> 2) * 1024 + bj * 4 + (s & 3);
            r += d_g2T[j * 32 + b] + bih[j] + bhh[j];
            gvs[s][b] = r;
        }
        __syncthreads();
        if (tid < 128) {   // cell update: 32 b x 4 h
            int b = tid >> 2, hh = tid & 3;
            int h = bj * 4 + hh;
            float iv = gvs[hh][b], fv = gvs[4 + hh][b];
            float gv = gvs[8 + hh][b], ov = gvs[12 + hh][b];
            float c = d_c[b * 1024 + h];
            float cn = sigf(fv) * c + sigf(iv) * tanhf(gv);
            float hn = sigf(ov) * tanhf(cn);
            d_c[b * 1024 + h] = cn;
            d_h[b * 1024 + h] = hn;
            d_hT[h * 32 + b] = hn;
        }
    }

    // ---- rec phase: tile bid owns j = bid*20 .. bid*20+19 ----
    if (dorec) {
        gridbar();
        float* ws = (float*)dsm;                       // [1024][20]
        float* ps = (float*)(dsm + 81920);             // [8][20][32]
        const int tile = bid;
        const float4* wb = (const float4*)(d_WrecB + (size_t)tile * 20480);
#pragma unroll
        for (int i = 0; i < 20; i++) ((float4*)ws)[tid + i * 256] = wb[tid + i * 256];
        __syncthreads();
        u64 acc[10];
#pragma unroll
        for (int q = 0; q < 10; q++) acc[q] = 0ull;
        const float* eb = d_hT + w * 128 * 32 + lane;
#pragma unroll 4
        for (int k = 0; k < 128; k++) {
            u64 ed = dup2f(eb[k * 32]);
            const ulonglong2* wrow = (const ulonglong2*)(ws + (w * 128 + k) * 20);
#pragma unroll
            for (int j = 0; j < 5; j++) {
                ulonglong2 t2 = wrow[j];
                ffma2(acc[2 * j], ed, t2.x); ffma2(acc[2 * j + 1], ed, t2.y);
            }
        }
#pragma unroll
        for (int q = 0; q < 10; q++) {
            float a2, b2; unpack2(acc[q], a2, b2);
            ps[(w * 20 + 2 * q) * 32 + lane] = a2;
            ps[(w * 20 + 2 * q + 1) * 32 + lane] = b2;
        }
        __syncthreads();
#pragma unroll
        for (int q = 0; q < 3; q++) {                  // 20 s x 32 b = 640 outs
            int idx = tid + q * 256;
            if (idx < 640) {
                int s = idx >> 5, b = idx & 31;
                float r = 0.0f;
#pragma unroll
                for (int w8 = 0; w8 < 8; w8++) r += ps[(w8 * 20 + s) * 32 + b];
                int j = tile * 20 + s;
                if (j < 4096) d_g2T[j * 32 + b] = r;
                else          d_hWhT[(j - 4096) * 32 + b] = r;
            }
        }
    }
}

// ---- final FC ----
__global__ __launch_bounds__(256) void k_fc(const float* __restrict__ Wfc,
                                            const float* __restrict__ bfc,
                                            float* __restrict__ out) {
    const int b = blockIdx.x, w = threadIdx.x >> 5, lane = threadIdx.x & 31;
    const float* hr = d_h + b * 1024;
    const float* wr = Wfc + w * 1024;
    float s = 0.0f;
    for (int i = lane * 4; i < 1024; i += 128) {
        float4 hv = *(const float4*)&hr[i];
        float4 wv = *(const float4*)&wr[i];
        s = fmaf(hv.x, wv.x, s); s = fmaf(hv.y, wv.y, s);
        s = fmaf(hv.z, wv.z, s); s = fmaf(hv.w, wv.w, s);
    }
#pragma unroll
    for (int off = 16; off; off >>= 1) s += __shfl_xor_sync(0xffffffffu, s, off);
    if (lane == 0) out[b * 8 + w] = s + bfc[w];
}

extern "C" void kernel_launch(void* const* d_in, const int* in_sizes, int n_in,
                              void* d_out, int out_size) {
    const float* x     = (const float*)d_in[0];
    const float* Wx    = (const float*)d_in[1];
    const float* Wh    = (const float*)d_in[2];
    const float* b_att = (const float*)d_in[3];
    const float* v     = (const float*)d_in[4];
    const float* Wih   = (const float*)d_in[5];
    const float* Whh   = (const float*)d_in[6];
    const float* bih   = (const float*)d_in[7];
    const float* bhh   = (const float*)d_in[8];
    const float* Wfc   = (const float*)d_in[9];
    const float* bfc   = (const float*)d_in[10];
    float* out = (float*)d_out;

    static int attr_set = 0;
    if (!attr_set) {
        cudaFuncSetAttribute(k_xe_mma, cudaFuncAttributeMaxDynamicSharedMemorySize, XE_SMEM);
        cudaFuncSetAttribute(k_step, cudaFuncAttributeMaxDynamicSharedMemorySize, STEP_SMEM);
        attr_set = 1;
    }

    k_init<<<512, 256>>>();
    k_prep_rec<<<dim3(256, 8), 256>>>(Whh, Wh);
    k_prep_ih<<<dim3(256, 8), 256>>>(Wih);
    k_cvt_x<<<20480, 256>>>(x);
    k_cvt_w<<<dim3(16, 32), 256>>>(Wx);
    k_xe_mma<<<1280, 256, XE_SMEM>>>();
    for (int t = 0; t < 64; t++) {
        k_attn<<<32, 1024>>>(t, x, b_att, v);
        k_step<<<256, 256, STEP_SMEM>>>(t < 63 ? 1 : 0, bih, bhh);
    }
    k_fc<<<32, 256>>>(Wfc, bfc, out);
}